// round 16
// baseline (speedup 1.0000x reference)
#include <cuda_runtime.h>
#include <math.h>

#define NN   50000
#define N2   (2 * NN)
#define NE_  800000
#define NB   4096
#define NEX  8
#define EMBD 64
#define E2M  131072
#define STILE 4096

// ---- device scratch ----
__device__ __align__(16) float g_z[N2 * 32];     // X @ (W1@W2), unscaled
__device__ __align__(16) float g_dv[N2 * 32];    // dinv * (A_hat z)
__device__ __align__(16) float g_r[N2];          // dinv*(sum dinv_in + dinv)
__device__ __align__(16) float g_W12[64 * 32];   // W1 @ W2
__device__ __align__(16) float g_c[32];          // b1 @ W2
__device__ __align__(16) float g_dinv[N2];
__device__ __align__(16) int   g_cnt_i[N2];
__device__ __align__(16) int   g_starts0[NN + 1];
__device__ __align__(16) int   g_starts1[NN + 1];
__device__ __align__(16) int   g_cursor0[NN];
__device__ __align__(16) int   g_cursor1[NN];
__device__ __align__(16) int   g_csr[2 * NE_];
__device__ __align__(16) float g_pool[NB * 64];
__device__ __align__(16) float g_cnt[2 * NB];
__device__ __align__(16) int   g_bins2[NB];
__device__ __align__(16) int   g_starts2[NB + 1];
__device__ __align__(16) int   g_cursor2[NB];
__device__ __align__(16) int   g_order[E2M];
__device__ __align__(16) float g_dsq[(size_t)E2M * NEX];
__device__ __align__(16) unsigned int g_st[3 * 32];
__device__ int   g_done[1];
__device__ float g_loss[1];

static __device__ __forceinline__ void red_add_v4(float4* p, float4 v) {
    asm volatile("red.global.add.v4.f32 [%0], {%1, %2, %3, %4};"
                 :: "l"(p), "f"(v.x), "f"(v.y), "f"(v.z), "f"(v.w)
                 : "memory");
}

// -------- W12 = W1@W2 (64x32) and c = b1@W2 (32), one block --------
__global__ void k_w12(const float* __restrict__ W1, const float* __restrict__ b1,
                      const float* __restrict__ W2) {
    int t = threadIdx.x;
    for (int idx = t; idx < 64 * 32; idx += blockDim.x) {
        int r = idx >> 5, cc = idx & 31;
        float s = 0.0f;
        for (int k = 0; k < 64; k++) s += W1[r * 64 + k] * W2[k * 32 + cc];
        g_W12[idx] = s;
    }
    if (t < 32) {
        float s = 0.0f;
        for (int k = 0; k < 64; k++) s += b1[k] * W2[k * 32 + t];
        g_c[t] = s;
    }
}

// -------- per-scale histogram (vectorized) --------
__global__ void k_histS(const int* __restrict__ dst, int* __restrict__ cnt, int E4) {
    int t = blockIdx.x * blockDim.x + threadIdx.x;
    if (t >= E4) return;
    int4 d = ((const int4*)dst)[t];
    atomicAdd(&cnt[d.x], 1);
    atomicAdd(&cnt[d.y], 1);
    atomicAdd(&cnt[d.z], 1);
    atomicAdd(&cnt[d.w], 1);
}

// ---------------- loss-edge histogram ----------------
__global__ void k_hist(const int* __restrict__ key, int* __restrict__ bins, int n) {
    int e = blockIdx.x * blockDim.x + threadIdx.x;
    if (e < n) atomicAdd(&bins[key[e]], 1);
}

// ========== single-kernel exclusive scan, decoupled lookback (unsigned states) ==========
__global__ void k_scanF(const int* __restrict__ cnt, int n,
                        int* __restrict__ starts, int* __restrict__ cursor,
                        float* __restrict__ dinv, int total, volatile unsigned int* st) {
    int b = blockIdx.x, t = threadIdx.x;
    long base = (long)b * STILE + (long)t * 16;
    int c[16];
    bool full = (base + 16 <= n);
    if (full) {
        const int4* p = (const int4*)(cnt + base);
        int4 a0 = p[0], a1 = p[1], a2 = p[2], a3 = p[3];
        c[0]=a0.x;c[1]=a0.y;c[2]=a0.z;c[3]=a0.w;
        c[4]=a1.x;c[5]=a1.y;c[6]=a1.z;c[7]=a1.w;
        c[8]=a2.x;c[9]=a2.y;c[10]=a2.z;c[11]=a2.w;
        c[12]=a3.x;c[13]=a3.y;c[14]=a3.z;c[15]=a3.w;
    } else {
        for (int k = 0; k < 16; k++) { long i = base + k; c[k] = (i < n) ? cnt[i] : 0; }
    }
    int pref[16];
    int s = 0;
#pragma unroll
    for (int k = 0; k < 16; k++) { pref[k] = s; s += c[k]; }
    __shared__ int sh[256];
    __shared__ int s_excl;
    sh[t] = s;
    __syncthreads();
    for (int o = 1; o < 256; o <<= 1) {
        int u = (t >= o) ? sh[t - o] : 0;
        __syncthreads();
        sh[t] += u;
        __syncthreads();
    }
    int blockTot = sh[255];
    if (t == 0) {
        __threadfence();
        st[b] = (1u << 30) | (unsigned int)blockTot;
        int excl = 0;
        int p = b - 1;
        while (p >= 0) {
            unsigned int v;
            do { v = st[p]; } while ((v >> 30) == 0u);
            if ((v >> 30) == 2u) { excl += (int)(v & 0x3FFFFFFFu); break; }
            excl += (int)(v & 0x3FFFFFFFu);
            p--;
        }
        __threadfence();
        st[b] = (2u << 30) | (unsigned int)(excl + blockTot);
        s_excl = excl;
    }
    __syncthreads();
    int off = s_excl + sh[t] - s;
    if (full) {
        int4 o4[4];
#pragma unroll
        for (int j = 0; j < 4; j++) {
            o4[j].x = off + pref[4*j];   o4[j].y = off + pref[4*j+1];
            o4[j].z = off + pref[4*j+2]; o4[j].w = off + pref[4*j+3];
        }
        int4* ps = (int4*)(starts + base);
        int4* pc = (int4*)(cursor + base);
#pragma unroll
        for (int j = 0; j < 4; j++) { ps[j] = o4[j]; pc[j] = o4[j]; }
        if (dinv) {
            float4* pd = (float4*)(dinv + base);
#pragma unroll
            for (int j = 0; j < 4; j++)
                pd[j] = make_float4(rsqrtf((float)c[4*j] + 1.0f),
                                    rsqrtf((float)c[4*j+1] + 1.0f),
                                    rsqrtf((float)c[4*j+2] + 1.0f),
                                    rsqrtf((float)c[4*j+3] + 1.0f));
        }
    } else {
        for (int k = 0; k < 16; k++) {
            long i = base + k;
            if (i < n) {
                int v = off + pref[k];
                starts[i] = v; cursor[i] = v;
                if (dinv) dinv[i] = rsqrtf((float)c[k] + 1.0f);
            }
        }
    }
    if (b == 0 && t == 0) starts[n] = total;
}

// -------- per-scale CSR fill (stores GLOBAL source ids), vectorized --------
__global__ void k_fillS(const int* __restrict__ src, const int* __restrict__ dst,
                        int* __restrict__ cursor, int* __restrict__ csr, int soff, int E4) {
    int t = blockIdx.x * blockDim.x + threadIdx.x;
    if (t >= E4) return;
    int4 s = ((const int4*)src)[t];
    int4 d = ((const int4*)dst)[t];
    csr[atomicAdd(&cursor[d.x], 1)] = s.x + soff;
    csr[atomicAdd(&cursor[d.y], 1)] = s.y + soff;
    csr[atomicAdd(&cursor[d.z], 1)] = s.z + soff;
    csr[atomicAdd(&cursor[d.w], 1)] = s.w + soff;
}

// ---------------- loss-edge bucket fill ----------------
__global__ void k_fill2(const int* __restrict__ srow, int E2) {
    int e = blockIdx.x * blockDim.x + threadIdx.x;
    if (e >= E2) return;
    int pos = atomicAdd(&g_cursor2[srow[e]], 1);
    g_order[pos] = e;
}

// ------- GEMM: g_z = X @ W12  (n2 x 32), 2 threads/row, 16 cols each -------
__global__ void k_gemmZ(const float* __restrict__ X0, const float* __restrict__ X1,
                        int splitN, int n2) {
    __shared__ float Ws[64 * 32];
    for (int i = threadIdx.x; i < 64 * 32; i += blockDim.x) Ws[i] = g_W12[i];
    __syncthreads();
    int idx = blockIdx.x * blockDim.x + threadIdx.x;
    int row = idx >> 1;
    int part = idx & 1;
    if (row >= n2) return;
    const float4* xr = (const float4*)((row < splitN)
                       ? (X0 + (size_t)row * 64)
                       : (X1 + (size_t)(row - splitN) * 64));
    float acc[16];
#pragma unroll
    for (int c = 0; c < 16; c++) acc[c] = 0.0f;
#pragma unroll 4
    for (int kk = 0; kk < 16; kk++) {
        float4 xv = xr[kk];
#pragma unroll
        for (int j = 0; j < 4; j++) {
            float xk = (j == 0) ? xv.x : (j == 1) ? xv.y : (j == 2) ? xv.z : xv.w;
            const float4* wrow = (const float4*)(Ws + (kk * 4 + j) * 32 + part * 16);
            float4 w0 = wrow[0], w1 = wrow[1], w2 = wrow[2], w3 = wrow[3];
            acc[0]  += xk*w0.x; acc[1]  += xk*w0.y; acc[2]  += xk*w0.z; acc[3]  += xk*w0.w;
            acc[4]  += xk*w1.x; acc[5]  += xk*w1.y; acc[6]  += xk*w1.z; acc[7]  += xk*w1.w;
            acc[8]  += xk*w2.x; acc[9]  += xk*w2.y; acc[10] += xk*w2.z; acc[11] += xk*w2.w;
            acc[12] += xk*w3.x; acc[13] += xk*w3.y; acc[14] += xk*w3.z; acc[15] += xk*w3.w;
        }
    }
    float4* y4 = (float4*)(g_z + (size_t)row * 32 + part * 16);
#pragma unroll
    for (int j = 0; j < 4; j++)
        y4[j] = make_float4(acc[4*j], acc[4*j+1], acc[4*j+2], acc[4*j+3]);
}

static __device__ __forceinline__ void node_range(int i, int& b0, int& b1, const int** csr) {
    if (i < NN) { b0 = g_starts0[i]; b1 = g_starts0[i + 1]; *csr = g_csr; }
    else        { b0 = g_starts1[i - NN]; b1 = g_starts1[i - NN + 1]; *csr = g_csr + NE_; }
}

// ------- gather pass 1: dv = dinv^2*(sum dinv_s z_s + dinv z_d);  r = dinv*(sum dinv_s + dinv) -------
__global__ void k_g1(int n2) {
    int idx = blockIdx.x * blockDim.x + threadIdx.x;
    int i = idx >> 3;
    int q = idx & 7;
    if (i >= n2) return;
    const float4* z4 = (const float4*)g_z;
    float di = g_dinv[i];
    float4 zs = z4[(size_t)i * 8 + q];
    float4 sum = make_float4(di * zs.x, di * zs.y, di * zs.z, di * zs.w);
    float rs = di;
    int b0, b1;
    const int* csr;
    node_range(i, b0, b1, &csr);
    int j = b0;
    for (; j + 3 < b1; j += 4) {
        int s0 = csr[j], s1 = csr[j+1], s2 = csr[j+2], s3 = csr[j+3];
        float d0 = g_dinv[s0], d1 = g_dinv[s1], d2 = g_dinv[s2], d3 = g_dinv[s3];
        float4 v0 = z4[(size_t)s0 * 8 + q];
        float4 v1 = z4[(size_t)s1 * 8 + q];
        float4 v2 = z4[(size_t)s2 * 8 + q];
        float4 v3 = z4[(size_t)s3 * 8 + q];
        sum.x += d0*v0.x + d1*v1.x + d2*v2.x + d3*v3.x;
        sum.y += d0*v0.y + d1*v1.y + d2*v2.y + d3*v3.y;
        sum.z += d0*v0.z + d1*v1.z + d2*v2.z + d3*v3.z;
        sum.w += d0*v0.w + d1*v1.w + d2*v2.w + d3*v3.w;
        rs += d0 + d1 + d2 + d3;
    }
    for (; j < b1; j++) {
        int s = csr[j];
        float ds = g_dinv[s];
        float4 v = z4[(size_t)s * 8 + q];
        sum.x += ds*v.x; sum.y += ds*v.y; sum.z += ds*v.z; sum.w += ds*v.w;
        rs += ds;
    }
    float d2i = di * di;
    ((float4*)g_dv)[(size_t)i * 8 + q] =
        make_float4(d2i * sum.x, d2i * sum.y, d2i * sum.z, d2i * sum.w);
    if (q == 0) g_r[i] = di * rs;
}

// ------- gather pass 2 + pool: h2 = dinv*(sum dv_s + dv_d) + r*c + b2 -------
__global__ void k_g2(const float* __restrict__ b2v, const int* __restrict__ bat0,
                     const int* __restrict__ bat1, int n2) {
    int idx = blockIdx.x * blockDim.x + threadIdx.x;
    int i = idx >> 3;
    int q = idx & 7;
    if (i >= n2) return;
    const float4* dv4 = (const float4*)g_dv;
    float4 acc = dv4[(size_t)i * 8 + q];
    int b0, b1;
    const int* csr;
    node_range(i, b0, b1, &csr);
    int j = b0;
    for (; j + 3 < b1; j += 4) {
        int s0 = csr[j], s1 = csr[j+1], s2 = csr[j+2], s3 = csr[j+3];
        float4 v0 = dv4[(size_t)s0 * 8 + q];
        float4 v1 = dv4[(size_t)s1 * 8 + q];
        float4 v2 = dv4[(size_t)s2 * 8 + q];
        float4 v3 = dv4[(size_t)s3 * 8 + q];
        acc.x += (v0.x + v1.x) + (v2.x + v3.x);
        acc.y += (v0.y + v1.y) + (v2.y + v3.y);
        acc.z += (v0.z + v1.z) + (v2.z + v3.z);
        acc.w += (v0.w + v1.w) + (v2.w + v3.w);
    }
    for (; j < b1; j++) {
        float4 v = dv4[(size_t)csr[j] * 8 + q];
        acc.x += v.x; acc.y += v.y; acc.z += v.z; acc.w += v.w;
    }
    float di = g_dinv[i];
    float r = g_r[i];
    float4 cq = ((const float4*)g_c)[q];
    float4 bq = ((const float4*)b2v)[q];
    float4 h2 = make_float4(di*acc.x + r*cq.x + bq.x,
                            di*acc.y + r*cq.y + bq.y,
                            di*acc.z + r*cq.z + bq.z,
                            di*acc.w + r*cq.w + bq.w);
    int scale = (i < NN) ? 0 : 1;
    int b = (i < NN) ? bat0[i] : bat1[i - NN];
    red_add_v4(((float4*)g_pool) + b * 16 + scale * 8 + q, h2);
}

// ---------------- per-graph node count, both scales ----------------
__global__ void k_cnt(const int* __restrict__ bat0, const int* __restrict__ bat1, int n2) {
    int i = blockIdx.x * blockDim.x + threadIdx.x;
    if (i >= n2) return;
    if (i < NN) atomicAdd(&g_cnt[bat0[i]], 1.0f);
    else        atomicAdd(&g_cnt[NB + bat1[i - NN]], 1.0f);
}

// ---------------- gate = softmax(concat(x0,x1) @ Wc + bc) ----------------
__global__ void k_gate(const float* __restrict__ Wc, const float* __restrict__ bc,
                       float* __restrict__ out, int B) {
    int b = blockIdx.x * blockDim.x + threadIdx.x;
    if (b >= B) return;
    float inv0 = 1.0f / fmaxf(g_cnt[b], 1.0f);
    float inv1 = 1.0f / fmaxf(g_cnt[NB + b], 1.0f);
    float logit[NEX];
#pragma unroll
    for (int e = 0; e < NEX; e++) logit[e] = bc[e];
    const float* pr = g_pool + b * 64;
    for (int k = 0; k < 64; k++) {
        float xv = pr[k] * (k < 32 ? inv0 : inv1);
#pragma unroll
        for (int e = 0; e < NEX; e++) logit[e] += xv * Wc[k * NEX + e];
    }
    float m = logit[0];
#pragma unroll
    for (int e = 1; e < NEX; e++) m = fmaxf(m, logit[e]);
    float ssum = 0.0f;
#pragma unroll
    for (int e = 0; e < NEX; e++) { logit[e] = expf(logit[e] - m); ssum += logit[e]; }
    float is = 1.0f / ssum;
#pragma unroll
    for (int e = 0; e < NEX; e++) out[b * NEX + e] = logit[e] * is;
}

// ---------- per-edge per-expert squared distance (gate-independent) ----------
__global__ void k_dsq(const float* __restrict__ emb, const int* __restrict__ ei2, int E2) {
    __shared__ float sa[NEX * EMBD];
    int g = blockIdx.x;
    int tid = threadIdx.x;
    for (int i = tid; i < NEX * EMBD; i += blockDim.x)
        sa[i] = emb[(size_t)g * (NEX * EMBD) + i];
    __syncthreads();

    int lane = tid & 31;
    int w = tid >> 5;
    int ex = lane >> 2;
    int ch = lane & 3;
    const float4* Ap = ((const float4*)sa) + ex * 16 + ch * 4;

    int b0 = g_starts2[g], b1 = g_starts2[g + 1];
    for (int j = b0 + w; j < b1; j += 8) {
        int e = g_order[j];
        int d = ei2[E2 + e];
        const float4* Bp = (const float4*)(emb + (size_t)d * (NEX * EMBD)) + ex * 16 + ch * 4;
        float acc = 0.0f;
#pragma unroll
        for (int k = 0; k < 4; k++) {
            float4 a = Ap[k], b = Bp[k];
            float dx = a.x - b.x, dy = a.y - b.y, dz = a.z - b.z, dw = a.w - b.w;
            acc += dx*dx + dy*dy + dz*dz + dw*dw;
        }
        acc += __shfl_xor_sync(0xffffffffu, acc, 1);
        acc += __shfl_xor_sync(0xffffffffu, acc, 2);
        if (ch == 0) g_dsq[(size_t)e * NEX + ex] = acc;
    }
}

// ---------- final loss ----------
__global__ void k_lossf(const float* __restrict__ gate, const float* __restrict__ dis,
                        const int* __restrict__ ei2, int E2,
                        float* __restrict__ lossp, float invE2) {
    __shared__ float wp[8];
    int tid = threadIdx.x;
    int gidx = blockIdx.x * blockDim.x + tid;
    int e = gidx >> 3;
    int le = tid & 7;
    float part = 0.0f;
    if (e < E2) {
        int s = ei2[e], d = ei2[E2 + e];
        float gp = gate[s * NEX + le] * gate[d * NEX + le];
        float dv = g_dsq[(size_t)e * NEX + le];
        float m = gp;
#pragma unroll
        for (int o = 1; o < 8; o <<= 1) m = fmaxf(m, __shfl_xor_sync(0xffffffffu, m, o, 8));
        float wgt = expf(gp - m);
        float sw = wgt;
#pragma unroll
        for (int o = 1; o < 8; o <<= 1) sw += __shfl_xor_sync(0xffffffffu, sw, o, 8);
        float num = dv * wgt;
#pragma unroll
        for (int o = 1; o < 8; o <<= 1) num += __shfl_xor_sync(0xffffffffu, num, o, 8);
        if (le == 0) part = fabsf(num / sw / dis[e] - 1.0f);
    }
#pragma unroll
    for (int o = 16; o > 0; o >>= 1) part += __shfl_xor_sync(0xffffffffu, part, o);
    if ((tid & 31) == 0) wp[tid >> 5] = part;
    __syncthreads();
    if (tid == 0) {
        float s = 0.0f;
#pragma unroll
        for (int k = 0; k < 8; k++) s += wp[k];
        atomicAdd(g_loss, s);
        __threadfence();
        int ticket = atomicAdd(g_done, 1);
        if (ticket == gridDim.x - 1) {
            float total = atomicAdd(g_loss, 0.0f);
            lossp[0] = total * invE2;
        }
    }
}

extern "C" void kernel_launch(void* const* d_in, const int* in_sizes, int n_in,
                              void* d_out, int out_size) {
    const float* x0   = (const float*)d_in[0];
    const float* x1   = (const float*)d_in[1];
    const float* W1   = (const float*)d_in[2];
    const float* b1   = (const float*)d_in[3];
    const float* W2   = (const float*)d_in[4];
    const float* b2   = (const float*)d_in[5];
    const float* Wc   = (const float*)d_in[6];
    const float* bc   = (const float*)d_in[7];
    const float* emb  = (const float*)d_in[8];
    const float* dis  = (const float*)d_in[9];
    const int*   ei0  = (const int*)d_in[10];
    const int*   ei1  = (const int*)d_in[11];
    const int*   bat0 = (const int*)d_in[12];
    const int*   bat1 = (const int*)d_in[13];
    const int*   ei2  = (const int*)d_in[14];

    int N  = in_sizes[0] / 64;
    int E  = in_sizes[10] / 2;
    int B  = in_sizes[8] / (NEX * EMBD);
    int E2 = in_sizes[14] / 2;
    int n2 = 2 * N;

    float* out = (float*)d_out;
    float* lossp = out + (out_size - 1);

    void *p_cnt_i, *p_starts0, *p_starts1, *p_cursor0, *p_cursor1, *p_dinv;
    void *p_pool, *p_cnt, *p_loss, *p_done, *p_csr, *p_st;
    void *p_bins2, *p_starts2, *p_cursor2;
    cudaGetSymbolAddress(&p_cnt_i,   g_cnt_i);
    cudaGetSymbolAddress(&p_starts0, g_starts0);
    cudaGetSymbolAddress(&p_starts1, g_starts1);
    cudaGetSymbolAddress(&p_cursor0, g_cursor0);
    cudaGetSymbolAddress(&p_cursor1, g_cursor1);
    cudaGetSymbolAddress(&p_dinv,    g_dinv);
    cudaGetSymbolAddress(&p_pool,    g_pool);
    cudaGetSymbolAddress(&p_cnt,     g_cnt);
    cudaGetSymbolAddress(&p_loss,    g_loss);
    cudaGetSymbolAddress(&p_done,    g_done);
    cudaGetSymbolAddress(&p_csr,     g_csr);
    cudaGetSymbolAddress(&p_st,      g_st);
    cudaGetSymbolAddress(&p_bins2,   g_bins2);
    cudaGetSymbolAddress(&p_starts2, g_starts2);
    cudaGetSymbolAddress(&p_cursor2, g_cursor2);

    static cudaStream_t s1 = 0, s2 = 0, s3 = 0;
    static cudaEvent_t evR = 0, ev1 = 0, ev2 = 0, evG = 0, evF1 = 0;
    if (!s1) {
        cudaStreamCreateWithFlags(&s1, cudaStreamNonBlocking);
        cudaStreamCreateWithFlags(&s2, cudaStreamNonBlocking);
        cudaStreamCreateWithFlags(&s3, cudaStreamNonBlocking);
        cudaEventCreateWithFlags(&evR,  cudaEventDisableTiming);
        cudaEventCreateWithFlags(&ev1,  cudaEventDisableTiming);
        cudaEventCreateWithFlags(&ev2,  cudaEventDisableTiming);
        cudaEventCreateWithFlags(&evG,  cudaEventDisableTiming);
        cudaEventCreateWithFlags(&evF1, cudaEventDisableTiming);
    }

    const int T = 256;
    int G  = (N + STILE - 1) / STILE;    // 13 blocks per scale
    int G2 = (B + STILE - 1) / STILE;    // 1
    int E4 = E / 4;

    cudaMemsetAsync(p_st, 0, (size_t)3 * 32 * sizeof(unsigned int));
    cudaEventRecord(evR, 0);

    // ---- s2: W12 -> z GEMM, then memsets + node counts ----
    cudaStreamWaitEvent(s2, evR, 0);
    k_w12<<<1, 256, 0, s2>>>(W1, b1, W2);
    k_gemmZ<<<((long)n2 * 2 + T - 1) / T, T, 0, s2>>>(x0, x1, N, n2);
    cudaEventRecord(evG, s2);
    cudaMemsetAsync(p_pool, 0, (size_t)NB * 64 * sizeof(float), s2);
    cudaMemsetAsync(p_cnt,  0, (size_t)2 * NB * sizeof(float), s2);
    cudaMemsetAsync(p_loss, 0, sizeof(float), s2);
    cudaMemsetAsync(p_done, 0, sizeof(int), s2);
    k_cnt<<<(n2 + T - 1) / T, T, 0, s2>>>(bat0, bat1, n2);
    cudaEventRecord(ev2, s2);

    // ---- s1: loss-edge bucketing + pre-gate dsq ----
    cudaStreamWaitEvent(s1, evR, 0);
    cudaMemsetAsync(p_bins2, 0, (size_t)NB * sizeof(int), s1);
    k_hist<<<(E2 + T - 1) / T, T, 0, s1>>>(ei2, (int*)p_bins2, E2);
    k_scanF<<<G2, 256, 0, s1>>>((const int*)p_bins2, B, (int*)p_starts2, (int*)p_cursor2,
                                (float*)0, E2, (volatile unsigned int*)((unsigned int*)p_st + 64));
    k_fill2<<<(E2 + T - 1) / T, T, 0, s1>>>(ei2, E2);
    k_dsq<<<B, 256, 0, s1>>>(emb, ei2, E2);
    cudaEventRecord(ev1, s1);

    // ---- s3: scale-1 CSR build (parallel with main's scale-0 build) ----
    cudaStreamWaitEvent(s3, evR, 0);
    cudaMemsetAsync((int*)p_cnt_i + N, 0, (size_t)N * sizeof(int), s3);
    k_histS<<<(E4 + T - 1) / T, T, 0, s3>>>(ei1 + E, (int*)p_cnt_i + N, E4);
    k_scanF<<<G, 256, 0, s3>>>((const int*)p_cnt_i + N, N, (int*)p_starts1, (int*)p_cursor1,
                               (float*)p_dinv + N, E, (volatile unsigned int*)((unsigned int*)p_st + 32));
    k_fillS<<<(E4 + T - 1) / T, T, 0, s3>>>(ei1, ei1 + E, (int*)p_cursor1,
                                            (int*)p_csr + E, N, E4);
    cudaEventRecord(evF1, s3);

    // ---- main: scale-0 CSR build, join, full-width gathers, gate, loss ----
    cudaMemsetAsync(p_cnt_i, 0, (size_t)N * sizeof(int));
    k_histS<<<(E4 + T - 1) / T, T>>>(ei0 + E, (int*)p_cnt_i, E4);
    k_scanF<<<G, 256>>>((const int*)p_cnt_i, N, (int*)p_starts0, (int*)p_cursor0,
                        (float*)p_dinv, E, (volatile unsigned int*)(unsigned int*)p_st);
    k_fillS<<<(E4 + T - 1) / T, T>>>(ei0, ei0 + E, (int*)p_cursor0, (int*)p_csr, 0, E4);
    cudaStreamWaitEvent(0, evG, 0);
    cudaStreamWaitEvent(0, evF1, 0);
    k_g1<<<((long)n2 * 8 + T - 1) / T, T>>>(n2);
    cudaStreamWaitEvent(0, ev2, 0);
    k_g2<<<((long)n2 * 8 + T - 1) / T, T>>>(b2, bat0, bat1, n2);
    k_gate<<<(B + T - 1) / T, T>>>(Wc, bc, out, B);
    cudaStreamWaitEvent(0, ev1, 0);
    int LB = ((long)E2 * 8 + T - 1) / T;
    k_lossf<<<LB, T>>>(out, dis, ei2, E2, lossp, 1.0f / (float)E2);
}

// round 17
// speedup vs baseline: 1.0843x; 1.0843x over previous
#include <cuda_runtime.h>
#include <cuda_fp16.h>
#include <math.h>

#define NN   50000
#define N2   (2 * NN)
#define NE_  800000
#define NB   4096
#define NEX  8
#define EMBD 64
#define E2M  131072
#define STILE 4096

// ---- device scratch ----
__device__ __align__(16) __half g_zh[N2 * 32];   // X @ (W1@W2), fp16
__device__ __align__(16) __half g_dvh[N2 * 32];  // dinv * (A_hat z), fp16
__device__ __align__(16) float g_r[N2];
__device__ __align__(16) float g_W12[64 * 32];
__device__ __align__(16) float g_c[32];
__device__ __align__(16) float g_dinv[N2];
__device__ __align__(16) int   g_cnt_i[N2];
__device__ __align__(16) int   g_starts0[NN + 1];
__device__ __align__(16) int   g_starts1[NN + 1];
__device__ __align__(16) int   g_cursor0[NN];
__device__ __align__(16) int   g_cursor1[NN];
__device__ __align__(16) int   g_csr[2 * NE_];
__device__ __align__(16) float g_pool[NB * 64];
__device__ __align__(16) float g_cnt[2 * NB];
__device__ __align__(16) int   g_bins2[NB];
__device__ __align__(16) int   g_starts2[NB + 1];
__device__ __align__(16) int   g_cursor2[NB];
__device__ __align__(16) int   g_order[E2M];
__device__ __align__(16) float g_dsq[(size_t)E2M * NEX];
__device__ __align__(16) unsigned int g_st[3 * 32];
__device__ int   g_done[1];
__device__ float g_loss[1];

static __device__ __forceinline__ void red_add_v4(float4* p, float4 v) {
    asm volatile("red.global.add.v4.f32 [%0], {%1, %2, %3, %4};"
                 :: "l"(p), "f"(v.x), "f"(v.y), "f"(v.z), "f"(v.w)
                 : "memory");
}

static __device__ __forceinline__ void h8_acc(uint4 u, float w, float* acc) {
    const __half2* h = (const __half2*)&u;
#pragma unroll
    for (int k = 0; k < 4; k++) {
        float2 f = __half22float2(h[k]);
        acc[2*k]   += w * f.x;
        acc[2*k+1] += w * f.y;
    }
}

static __device__ __forceinline__ uint4 f8_to_h8(const float* f) {
    uint4 u;
    __half2* h = (__half2*)&u;
#pragma unroll
    for (int k = 0; k < 4; k++)
        h[k] = __floats2half2_rn(f[2*k], f[2*k+1]);
    return u;
}

// -------- W12 = W1@W2 (64x32) and c = b1@W2 (32), one block --------
__global__ void k_w12(const float* __restrict__ W1, const float* __restrict__ b1,
                      const float* __restrict__ W2) {
    int t = threadIdx.x;
    for (int idx = t; idx < 64 * 32; idx += blockDim.x) {
        int r = idx >> 5, cc = idx & 31;
        float s = 0.0f;
        for (int k = 0; k < 64; k++) s += W1[r * 64 + k] * W2[k * 32 + cc];
        g_W12[idx] = s;
    }
    if (t < 32) {
        float s = 0.0f;
        for (int k = 0; k < 64; k++) s += b1[k] * W2[k * 32 + t];
        g_c[t] = s;
    }
}

// -------- per-scale histogram (vectorized) --------
__global__ void k_histS(const int* __restrict__ dst, int* __restrict__ cnt, int E4) {
    int t = blockIdx.x * blockDim.x + threadIdx.x;
    if (t >= E4) return;
    int4 d = ((const int4*)dst)[t];
    atomicAdd(&cnt[d.x], 1);
    atomicAdd(&cnt[d.y], 1);
    atomicAdd(&cnt[d.z], 1);
    atomicAdd(&cnt[d.w], 1);
}

// ---------------- loss-edge histogram ----------------
__global__ void k_hist(const int* __restrict__ key, int* __restrict__ bins, int n) {
    int e = blockIdx.x * blockDim.x + threadIdx.x;
    if (e < n) atomicAdd(&bins[key[e]], 1);
}

// ========== single-kernel exclusive scan, decoupled lookback ==========
__global__ void k_scanF(const int* __restrict__ cnt, int n,
                        int* __restrict__ starts, int* __restrict__ cursor,
                        float* __restrict__ dinv, int total, volatile unsigned int* st) {
    int b = blockIdx.x, t = threadIdx.x;
    long base = (long)b * STILE + (long)t * 16;
    int c[16];
    bool full = (base + 16 <= n);
    if (full) {
        const int4* p = (const int4*)(cnt + base);
        int4 a0 = p[0], a1 = p[1], a2 = p[2], a3 = p[3];
        c[0]=a0.x;c[1]=a0.y;c[2]=a0.z;c[3]=a0.w;
        c[4]=a1.x;c[5]=a1.y;c[6]=a1.z;c[7]=a1.w;
        c[8]=a2.x;c[9]=a2.y;c[10]=a2.z;c[11]=a2.w;
        c[12]=a3.x;c[13]=a3.y;c[14]=a3.z;c[15]=a3.w;
    } else {
        for (int k = 0; k < 16; k++) { long i = base + k; c[k] = (i < n) ? cnt[i] : 0; }
    }
    int pref[16];
    int s = 0;
#pragma unroll
    for (int k = 0; k < 16; k++) { pref[k] = s; s += c[k]; }
    __shared__ int sh[256];
    __shared__ int s_excl;
    sh[t] = s;
    __syncthreads();
    for (int o = 1; o < 256; o <<= 1) {
        int u = (t >= o) ? sh[t - o] : 0;
        __syncthreads();
        sh[t] += u;
        __syncthreads();
    }
    int blockTot = sh[255];
    if (t == 0) {
        __threadfence();
        st[b] = (1u << 30) | (unsigned int)blockTot;
        int excl = 0;
        int p = b - 1;
        while (p >= 0) {
            unsigned int v;
            do { v = st[p]; } while ((v >> 30) == 0u);
            if ((v >> 30) == 2u) { excl += (int)(v & 0x3FFFFFFFu); break; }
            excl += (int)(v & 0x3FFFFFFFu);
            p--;
        }
        __threadfence();
        st[b] = (2u << 30) | (unsigned int)(excl + blockTot);
        s_excl = excl;
    }
    __syncthreads();
    int off = s_excl + sh[t] - s;
    if (full) {
        int4 o4[4];
#pragma unroll
        for (int j = 0; j < 4; j++) {
            o4[j].x = off + pref[4*j];   o4[j].y = off + pref[4*j+1];
            o4[j].z = off + pref[4*j+2]; o4[j].w = off + pref[4*j+3];
        }
        int4* ps = (int4*)(starts + base);
        int4* pc = (int4*)(cursor + base);
#pragma unroll
        for (int j = 0; j < 4; j++) { ps[j] = o4[j]; pc[j] = o4[j]; }
        if (dinv) {
            float4* pd = (float4*)(dinv + base);
#pragma unroll
            for (int j = 0; j < 4; j++)
                pd[j] = make_float4(rsqrtf((float)c[4*j] + 1.0f),
                                    rsqrtf((float)c[4*j+1] + 1.0f),
                                    rsqrtf((float)c[4*j+2] + 1.0f),
                                    rsqrtf((float)c[4*j+3] + 1.0f));
        }
    } else {
        for (int k = 0; k < 16; k++) {
            long i = base + k;
            if (i < n) {
                int v = off + pref[k];
                starts[i] = v; cursor[i] = v;
                if (dinv) dinv[i] = rsqrtf((float)c[k] + 1.0f);
            }
        }
    }
    if (b == 0 && t == 0) starts[n] = total;
}

// -------- per-scale CSR fill (stores GLOBAL source ids), vectorized --------
__global__ void k_fillS(const int* __restrict__ src, const int* __restrict__ dst,
                        int* __restrict__ cursor, int* __restrict__ csr, int soff, int E4) {
    int t = blockIdx.x * blockDim.x + threadIdx.x;
    if (t >= E4) return;
    int4 s = ((const int4*)src)[t];
    int4 d = ((const int4*)dst)[t];
    csr[atomicAdd(&cursor[d.x], 1)] = s.x + soff;
    csr[atomicAdd(&cursor[d.y], 1)] = s.y + soff;
    csr[atomicAdd(&cursor[d.z], 1)] = s.z + soff;
    csr[atomicAdd(&cursor[d.w], 1)] = s.w + soff;
}

// ---------------- loss-edge bucket fill ----------------
__global__ void k_fill2(const int* __restrict__ srow, int E2) {
    int e = blockIdx.x * blockDim.x + threadIdx.x;
    if (e >= E2) return;
    int pos = atomicAdd(&g_cursor2[srow[e]], 1);
    g_order[pos] = e;
}

// ------- GEMM: g_zh = half(X @ W12)  (n2 x 32), 2 threads/row, 16 cols each -------
__global__ void k_gemmZ(const float* __restrict__ X0, const float* __restrict__ X1,
                        int splitN, int n2) {
    __shared__ float Ws[64 * 32];
    for (int i = threadIdx.x; i < 64 * 32; i += blockDim.x) Ws[i] = g_W12[i];
    __syncthreads();
    int idx = blockIdx.x * blockDim.x + threadIdx.x;
    int row = idx >> 1;
    int part = idx & 1;
    if (row >= n2) return;
    const float4* xr = (const float4*)((row < splitN)
                       ? (X0 + (size_t)row * 64)
                       : (X1 + (size_t)(row - splitN) * 64));
    float acc[16];
#pragma unroll
    for (int c = 0; c < 16; c++) acc[c] = 0.0f;
#pragma unroll 4
    for (int kk = 0; kk < 16; kk++) {
        float4 xv = xr[kk];
#pragma unroll
        for (int j = 0; j < 4; j++) {
            float xk = (j == 0) ? xv.x : (j == 1) ? xv.y : (j == 2) ? xv.z : xv.w;
            const float4* wrow = (const float4*)(Ws + (kk * 4 + j) * 32 + part * 16);
            float4 w0 = wrow[0], w1 = wrow[1], w2 = wrow[2], w3 = wrow[3];
            acc[0]  += xk*w0.x; acc[1]  += xk*w0.y; acc[2]  += xk*w0.z; acc[3]  += xk*w0.w;
            acc[4]  += xk*w1.x; acc[5]  += xk*w1.y; acc[6]  += xk*w1.z; acc[7]  += xk*w1.w;
            acc[8]  += xk*w2.x; acc[9]  += xk*w2.y; acc[10] += xk*w2.z; acc[11] += xk*w2.w;
            acc[12] += xk*w3.x; acc[13] += xk*w3.y; acc[14] += xk*w3.z; acc[15] += xk*w3.w;
        }
    }
    uint4* y = (uint4*)(g_zh + (size_t)row * 32 + part * 16);
    y[0] = f8_to_h8(acc);
    y[1] = f8_to_h8(acc + 8);
}

static __device__ __forceinline__ void node_range(int i, int& b0, int& b1, const int** csr) {
    if (i < NN) { b0 = g_starts0[i]; b1 = g_starts0[i + 1]; *csr = g_csr; }
    else        { b0 = g_starts1[i - NN]; b1 = g_starts1[i - NN + 1]; *csr = g_csr + NE_; }
}

// ------- gather pass 1 (fp16 z): dv = dinv^2*(sum dinv_s z_s + dinv z_d); r -------
// 4 threads/node, 8 channels each
__global__ void k_g1(int n2) {
    int idx = blockIdx.x * blockDim.x + threadIdx.x;
    int i = idx >> 2;
    int q = idx & 3;
    if (i >= n2) return;
    const uint4* z4 = (const uint4*)g_zh;   // node row = 4 uint4
    float di = g_dinv[i];
    float acc[8];
#pragma unroll
    for (int k = 0; k < 8; k++) acc[k] = 0.0f;
    h8_acc(z4[(size_t)i * 4 + q], di, acc);   // self
    float rs = di;
    int b0, b1;
    const int* csr;
    node_range(i, b0, b1, &csr);
    int j = b0;
    for (; j + 3 < b1; j += 4) {
        int s0 = csr[j], s1 = csr[j+1], s2 = csr[j+2], s3 = csr[j+3];
        float d0 = g_dinv[s0], d1 = g_dinv[s1], d2 = g_dinv[s2], d3 = g_dinv[s3];
        uint4 u0 = z4[(size_t)s0 * 4 + q];
        uint4 u1 = z4[(size_t)s1 * 4 + q];
        uint4 u2 = z4[(size_t)s2 * 4 + q];
        uint4 u3 = z4[(size_t)s3 * 4 + q];
        h8_acc(u0, d0, acc);
        h8_acc(u1, d1, acc);
        h8_acc(u2, d2, acc);
        h8_acc(u3, d3, acc);
        rs += d0 + d1 + d2 + d3;
    }
    for (; j < b1; j++) {
        int s = csr[j];
        float ds = g_dinv[s];
        h8_acc(z4[(size_t)s * 4 + q], ds, acc);
        rs += ds;
    }
    float d2i = di * di;
#pragma unroll
    for (int k = 0; k < 8; k++) acc[k] *= d2i;
    ((uint4*)g_dvh)[(size_t)i * 4 + q] = f8_to_h8(acc);
    if (q == 0) g_r[i] = di * rs;
}

// ------- gather pass 2 (fp16 dv) + pool -------
__global__ void k_g2(const float* __restrict__ b2v, const int* __restrict__ bat0,
                     const int* __restrict__ bat1, int n2) {
    int idx = blockIdx.x * blockDim.x + threadIdx.x;
    int i = idx >> 2;
    int q = idx & 3;
    if (i >= n2) return;
    const uint4* dv4 = (const uint4*)g_dvh;
    float acc[8];
#pragma unroll
    for (int k = 0; k < 8; k++) acc[k] = 0.0f;
    h8_acc(dv4[(size_t)i * 4 + q], 1.0f, acc);  // self
    int b0, b1;
    const int* csr;
    node_range(i, b0, b1, &csr);
    int j = b0;
    for (; j + 3 < b1; j += 4) {
        uint4 u0 = dv4[(size_t)csr[j]   * 4 + q];
        uint4 u1 = dv4[(size_t)csr[j+1] * 4 + q];
        uint4 u2 = dv4[(size_t)csr[j+2] * 4 + q];
        uint4 u3 = dv4[(size_t)csr[j+3] * 4 + q];
        h8_acc(u0, 1.0f, acc);
        h8_acc(u1, 1.0f, acc);
        h8_acc(u2, 1.0f, acc);
        h8_acc(u3, 1.0f, acc);
    }
    for (; j < b1; j++)
        h8_acc(dv4[(size_t)csr[j] * 4 + q], 1.0f, acc);
    float di = g_dinv[i];
    float r = g_r[i];
    float h2[8];
#pragma unroll
    for (int k = 0; k < 8; k++) {
        int ch = q * 8 + k;
        h2[k] = di * acc[k] + r * g_c[ch] + b2v[ch];
    }
    int scale = (i < NN) ? 0 : 1;
    int b = (i < NN) ? bat0[i] : bat1[i - NN];
    float4* pp = ((float4*)g_pool) + b * 16 + scale * 8 + q * 2;
    red_add_v4(pp,     make_float4(h2[0], h2[1], h2[2], h2[3]));
    red_add_v4(pp + 1, make_float4(h2[4], h2[5], h2[6], h2[7]));
}

// ---------------- per-graph node count, both scales ----------------
__global__ void k_cnt(const int* __restrict__ bat0, const int* __restrict__ bat1, int n2) {
    int i = blockIdx.x * blockDim.x + threadIdx.x;
    if (i >= n2) return;
    if (i < NN) atomicAdd(&g_cnt[bat0[i]], 1.0f);
    else        atomicAdd(&g_cnt[NB + bat1[i - NN]], 1.0f);
}

// ---------------- gate = softmax(concat(x0,x1) @ Wc + bc) ----------------
__global__ void k_gate(const float* __restrict__ Wc, const float* __restrict__ bc,
                       float* __restrict__ out, int B) {
    int b = blockIdx.x * blockDim.x + threadIdx.x;
    if (b >= B) return;
    float inv0 = 1.0f / fmaxf(g_cnt[b], 1.0f);
    float inv1 = 1.0f / fmaxf(g_cnt[NB + b], 1.0f);
    float logit[NEX];
#pragma unroll
    for (int e = 0; e < NEX; e++) logit[e] = bc[e];
    const float* pr = g_pool + b * 64;
    for (int k = 0; k < 64; k++) {
        float xv = pr[k] * (k < 32 ? inv0 : inv1);
#pragma unroll
        for (int e = 0; e < NEX; e++) logit[e] += xv * Wc[k * NEX + e];
    }
    float m = logit[0];
#pragma unroll
    for (int e = 1; e < NEX; e++) m = fmaxf(m, logit[e]);
    float ssum = 0.0f;
#pragma unroll
    for (int e = 0; e < NEX; e++) { logit[e] = expf(logit[e] - m); ssum += logit[e]; }
    float is = 1.0f / ssum;
#pragma unroll
    for (int e = 0; e < NEX; e++) out[b * NEX + e] = logit[e] * is;
}

// ---------- per-edge per-expert squared distance (gate-independent) ----------
__global__ void k_dsq(const float* __restrict__ emb, const int* __restrict__ ei2, int E2) {
    __shared__ float sa[NEX * EMBD];
    int g = blockIdx.x;
    int tid = threadIdx.x;
    for (int i = tid; i < NEX * EMBD; i += blockDim.x)
        sa[i] = emb[(size_t)g * (NEX * EMBD) + i];
    __syncthreads();

    int lane = tid & 31;
    int w = tid >> 5;
    int ex = lane >> 2;
    int ch = lane & 3;
    const float4* Ap = ((const float4*)sa) + ex * 16 + ch * 4;

    int b0 = g_starts2[g], b1 = g_starts2[g + 1];
    for (int j = b0 + w; j < b1; j += 8) {
        int e = g_order[j];
        int d = ei2[E2 + e];
        const float4* Bp = (const float4*)(emb + (size_t)d * (NEX * EMBD)) + ex * 16 + ch * 4;
        float acc = 0.0f;
#pragma unroll
        for (int k = 0; k < 4; k++) {
            float4 a = Ap[k], b = Bp[k];
            float dx = a.x - b.x, dy = a.y - b.y, dz = a.z - b.z, dw = a.w - b.w;
            acc += dx*dx + dy*dy + dz*dz + dw*dw;
        }
        acc += __shfl_xor_sync(0xffffffffu, acc, 1);
        acc += __shfl_xor_sync(0xffffffffu, acc, 2);
        if (ch == 0) g_dsq[(size_t)e * NEX + ex] = acc;
    }
}

// ---------- final loss ----------
__global__ void k_lossf(const float* __restrict__ gate, const float* __restrict__ dis,
                        const int* __restrict__ ei2, int E2,
                        float* __restrict__ lossp, float invE2) {
    __shared__ float wp[8];
    int tid = threadIdx.x;
    int gidx = blockIdx.x * blockDim.x + tid;
    int e = gidx >> 3;
    int le = tid & 7;
    float part = 0.0f;
    if (e < E2) {
        int s = ei2[e], d = ei2[E2 + e];
        float gp = gate[s * NEX + le] * gate[d * NEX + le];
        float dv = g_dsq[(size_t)e * NEX + le];
        float m = gp;
#pragma unroll
        for (int o = 1; o < 8; o <<= 1) m = fmaxf(m, __shfl_xor_sync(0xffffffffu, m, o, 8));
        float wgt = expf(gp - m);
        float sw = wgt;
#pragma unroll
        for (int o = 1; o < 8; o <<= 1) sw += __shfl_xor_sync(0xffffffffu, sw, o, 8);
        float num = dv * wgt;
#pragma unroll
        for (int o = 1; o < 8; o <<= 1) num += __shfl_xor_sync(0xffffffffu, num, o, 8);
        if (le == 0) part = fabsf(num / sw / dis[e] - 1.0f);
    }
#pragma unroll
    for (int o = 16; o > 0; o >>= 1) part += __shfl_xor_sync(0xffffffffu, part, o);
    if ((tid & 31) == 0) wp[tid >> 5] = part;
    __syncthreads();
    if (tid == 0) {
        float s = 0.0f;
#pragma unroll
        for (int k = 0; k < 8; k++) s += wp[k];
        atomicAdd(g_loss, s);
        __threadfence();
        int ticket = atomicAdd(g_done, 1);
        if (ticket == gridDim.x - 1) {
            float total = atomicAdd(g_loss, 0.0f);
            lossp[0] = total * invE2;
        }
    }
}

extern "C" void kernel_launch(void* const* d_in, const int* in_sizes, int n_in,
                              void* d_out, int out_size) {
    const float* x0   = (const float*)d_in[0];
    const float* x1   = (const float*)d_in[1];
    const float* W1   = (const float*)d_in[2];
    const float* b1   = (const float*)d_in[3];
    const float* W2   = (const float*)d_in[4];
    const float* b2   = (const float*)d_in[5];
    const float* Wc   = (const float*)d_in[6];
    const float* bc   = (const float*)d_in[7];
    const float* emb  = (const float*)d_in[8];
    const float* dis  = (const float*)d_in[9];
    const int*   ei0  = (const int*)d_in[10];
    const int*   ei1  = (const int*)d_in[11];
    const int*   bat0 = (const int*)d_in[12];
    const int*   bat1 = (const int*)d_in[13];
    const int*   ei2  = (const int*)d_in[14];

    int N  = in_sizes[0] / 64;
    int E  = in_sizes[10] / 2;
    int B  = in_sizes[8] / (NEX * EMBD);
    int E2 = in_sizes[14] / 2;
    int n2 = 2 * N;

    float* out = (float*)d_out;
    float* lossp = out + (out_size - 1);

    void *p_cnt_i, *p_starts0, *p_starts1, *p_cursor0, *p_cursor1, *p_dinv;
    void *p_pool, *p_cnt, *p_loss, *p_done, *p_csr, *p_st;
    void *p_bins2, *p_starts2, *p_cursor2;
    cudaGetSymbolAddress(&p_cnt_i,   g_cnt_i);
    cudaGetSymbolAddress(&p_starts0, g_starts0);
    cudaGetSymbolAddress(&p_starts1, g_starts1);
    cudaGetSymbolAddress(&p_cursor0, g_cursor0);
    cudaGetSymbolAddress(&p_cursor1, g_cursor1);
    cudaGetSymbolAddress(&p_dinv,    g_dinv);
    cudaGetSymbolAddress(&p_pool,    g_pool);
    cudaGetSymbolAddress(&p_cnt,     g_cnt);
    cudaGetSymbolAddress(&p_loss,    g_loss);
    cudaGetSymbolAddress(&p_done,    g_done);
    cudaGetSymbolAddress(&p_csr,     g_csr);
    cudaGetSymbolAddress(&p_st,      g_st);
    cudaGetSymbolAddress(&p_bins2,   g_bins2);
    cudaGetSymbolAddress(&p_starts2, g_starts2);
    cudaGetSymbolAddress(&p_cursor2, g_cursor2);

    static cudaStream_t s1 = 0, s2 = 0, s3 = 0;
    static cudaEvent_t evR = 0, ev1 = 0, ev2 = 0, evG = 0, evF1 = 0;
    if (!s1) {
        cudaStreamCreateWithFlags(&s1, cudaStreamNonBlocking);
        cudaStreamCreateWithFlags(&s2, cudaStreamNonBlocking);
        cudaStreamCreateWithFlags(&s3, cudaStreamNonBlocking);
        cudaEventCreateWithFlags(&evR,  cudaEventDisableTiming);
        cudaEventCreateWithFlags(&ev1,  cudaEventDisableTiming);
        cudaEventCreateWithFlags(&ev2,  cudaEventDisableTiming);
        cudaEventCreateWithFlags(&evG,  cudaEventDisableTiming);
        cudaEventCreateWithFlags(&evF1, cudaEventDisableTiming);
    }

    const int T = 256;
    int G  = (N + STILE - 1) / STILE;
    int G2 = (B + STILE - 1) / STILE;
    int E4 = E / 4;

    cudaMemsetAsync(p_st, 0, (size_t)3 * 32 * sizeof(unsigned int));
    cudaEventRecord(evR, 0);

    // ---- s2: W12 -> z GEMM (fp16 out), then memsets + node counts ----
    cudaStreamWaitEvent(s2, evR, 0);
    k_w12<<<1, 256, 0, s2>>>(W1, b1, W2);
    k_gemmZ<<<((long)n2 * 2 + T - 1) / T, T, 0, s2>>>(x0, x1, N, n2);
    cudaEventRecord(evG, s2);
    cudaMemsetAsync(p_pool, 0, (size_t)NB * 64 * sizeof(float), s2);
    cudaMemsetAsync(p_cnt,  0, (size_t)2 * NB * sizeof(float), s2);
    cudaMemsetAsync(p_loss, 0, sizeof(float), s2);
    cudaMemsetAsync(p_done, 0, sizeof(int), s2);
    k_cnt<<<(n2 + T - 1) / T, T, 0, s2>>>(bat0, bat1, n2);
    cudaEventRecord(ev2, s2);

    // ---- s1: loss-edge bucketing + pre-gate dsq ----
    cudaStreamWaitEvent(s1, evR, 0);
    cudaMemsetAsync(p_bins2, 0, (size_t)NB * sizeof(int), s1);
    k_hist<<<(E2 + T - 1) / T, T, 0, s1>>>(ei2, (int*)p_bins2, E2);
    k_scanF<<<G2, 256, 0, s1>>>((const int*)p_bins2, B, (int*)p_starts2, (int*)p_cursor2,
                                (float*)0, E2, (volatile unsigned int*)((unsigned int*)p_st + 64));
    k_fill2<<<(E2 + T - 1) / T, T, 0, s1>>>(ei2, E2);
    k_dsq<<<B, 256, 0, s1>>>(emb, ei2, E2);
    cudaEventRecord(ev1, s1);

    // ---- s3: scale-1 CSR build ----
    cudaStreamWaitEvent(s3, evR, 0);
    cudaMemsetAsync((int*)p_cnt_i + N, 0, (size_t)N * sizeof(int), s3);
    k_histS<<<(E4 + T - 1) / T, T, 0, s3>>>(ei1 + E, (int*)p_cnt_i + N, E4);
    k_scanF<<<G, 256, 0, s3>>>((const int*)p_cnt_i + N, N, (int*)p_starts1, (int*)p_cursor1,
                               (float*)p_dinv + N, E, (volatile unsigned int*)((unsigned int*)p_st + 32));
    k_fillS<<<(E4 + T - 1) / T, T, 0, s3>>>(ei1, ei1 + E, (int*)p_cursor1,
                                            (int*)p_csr + E, N, E4);
    cudaEventRecord(evF1, s3);

    // ---- main: scale-0 CSR build, join, gathers, gate, loss ----
    cudaMemsetAsync(p_cnt_i, 0, (size_t)N * sizeof(int));
    k_histS<<<(E4 + T - 1) / T, T>>>(ei0 + E, (int*)p_cnt_i, E4);
    k_scanF<<<G, 256>>>((const int*)p_cnt_i, N, (int*)p_starts0, (int*)p_cursor0,
                        (float*)p_dinv, E, (volatile unsigned int*)(unsigned int*)p_st);
    k_fillS<<<(E4 + T - 1) / T, T>>>(ei0, ei0 + E, (int*)p_cursor0, (int*)p_csr, 0, E4);
    cudaStreamWaitEvent(0, evG, 0);
    cudaStreamWaitEvent(0, evF1, 0);
    k_g1<<<((long)n2 * 4 + T - 1) / T, T>>>(n2);
    cudaStreamWaitEvent(0, ev2, 0);
    k_g2<<<((long)n2 * 4 + T - 1) / T, T>>>(b2, bat0, bat1, n2);
    k_gate<<<(B + T - 1) / T, T>>>(Wc, bc, out, B);
    cudaStreamWaitEvent(0, ev1, 0);
    int LB = ((long)E2 * 8 + T - 1) / T;
    k_lossf<<<LB, T>>>(out, dis, ei2, E2, lossp, 1.0f / (float)E2);
}